// round 9
// baseline (speedup 1.0000x reference)
#include <cuda_runtime.h>
#include <cuda_fp16.h>

typedef unsigned long long ull;

#define Nn 20000
#define Dd 64
#define OUTC 64
#define WIDTH 2048   // B*D elements per node-row
#define Ee 640000
#define RPB 8
#define YPAD 68
#define NT 256

// ---------------- device scratch ----------------
__device__ __half g_X16[(size_t)Nn * WIDTH];   // 82 MB, fp16 x0
__device__ __half g_Y16[(size_t)Nn * WIDTH];   // 82 MB, fp16 A*x per support
__device__ int   g_rowptr[2][Nn + 1];
__device__ int   g_cnt[2][Nn];
__device__ int   g_fill[2][Nn];
__device__ int   g_cols[2][Ee];
__device__ float g_vals[2][Ee];
__device__ float g_Wc[Dd * OUTC];              // W0 + W3

// ---------------- packed f32x2 helpers ----------------
__device__ __forceinline__ ull pack2(float a, float b) {
    ull r; asm("mov.b64 %0, {%1, %2};" : "=l"(r) : "f"(a), "f"(b)); return r;
}
__device__ __forceinline__ void unpack2(float& a, float& b, ull p) {
    asm("mov.b64 {%0, %1}, %2;" : "=f"(a), "=f"(b) : "l"(p));
}
__device__ __forceinline__ void ffma2(ull& acc, ull a, ull b) {
    asm("fma.rn.f32x2 %0, %1, %2, %0;" : "+l"(acc) : "l"(a), "l"(b));
}

// ---------------- CSR build ----------------
__global__ void zero_counts_k() {
    int i = blockIdx.x * blockDim.x + threadIdx.x;
    if (i < 2 * Nn) { ((int*)g_cnt)[i] = 0; ((int*)g_fill)[i] = 0; }
}

__global__ void hist_k(const int* __restrict__ r0, const int* __restrict__ r1) {
    int i = blockIdx.x * blockDim.x + threadIdx.x;
    if (i < Ee)          atomicAdd(&g_cnt[0][r0[i]], 1);
    else if (i < 2 * Ee) atomicAdd(&g_cnt[1][r1[i - Ee]], 1);
}

__global__ void scan_k() {
    __shared__ int sums[1024];
    int s = blockIdx.x, t = threadIdx.x;
    const int CH = (Nn + 1023) / 1024;
    int base = t * CH, acc = 0;
    for (int i = 0; i < CH; i++) { int idx = base + i; if (idx < Nn) acc += g_cnt[s][idx]; }
    sums[t] = acc;
    __syncthreads();
    for (int off = 1; off < 1024; off <<= 1) {
        int v = (t >= off) ? sums[t - off] : 0;
        __syncthreads(); sums[t] += v; __syncthreads();
    }
    int run = (t > 0) ? sums[t - 1] : 0;
    for (int i = 0; i < CH; i++) {
        int idx = base + i;
        if (idx < Nn) { g_rowptr[s][idx] = run; run += g_cnt[s][idx]; }
    }
    if (t == 1023) g_rowptr[s][Nn] = sums[1023];
}

__global__ void scatter_k(const int* __restrict__ r0, const int* __restrict__ c0, const float* __restrict__ v0,
                          const int* __restrict__ r1, const int* __restrict__ c1, const float* __restrict__ v1) {
    int i = blockIdx.x * blockDim.x + threadIdx.x;
    int s, e; const int* rs; const int* cs; const float* vs;
    if (i < Ee)          { s = 0; e = i;      rs = r0; cs = c0; vs = v0; }
    else if (i < 2 * Ee) { s = 1; e = i - Ee; rs = r1; cs = c1; vs = v1; }
    else return;
    int row = rs[e];
    int pos = g_rowptr[s][row] + atomicAdd(&g_fill[s][row], 1);
    g_cols[s][pos] = cs[e];
    g_vals[s][pos] = vs[e];
}

__global__ void wc_k(const float* __restrict__ w) {
    int i = blockIdx.x * blockDim.x + threadIdx.x;
    if (i < Dd * OUTC) g_Wc[i] = w[i] + w[3 * Dd * OUTC + i];
}

// ---------------- gather accumulate (8 halves / thread / edge) ----------------
__device__ __forceinline__ void gacc(float acc[8], float v, const __half* __restrict__ src,
                                     int c, int t) {
    uint4 h = *(const uint4*)(src + (size_t)c * WIDTH + t * 8);
    const __half2* hp = (const __half2*)&h;
    float2 f0 = __half22float2(hp[0]);
    float2 f1 = __half22float2(hp[1]);
    float2 f2 = __half22float2(hp[2]);
    float2 f3 = __half22float2(hp[3]);
    acc[0] = fmaf(v, f0.x, acc[0]); acc[1] = fmaf(v, f0.y, acc[1]);
    acc[2] = fmaf(v, f1.x, acc[2]); acc[3] = fmaf(v, f1.y, acc[3]);
    acc[4] = fmaf(v, f2.x, acc[4]); acc[5] = fmaf(v, f2.y, acc[5]);
    acc[6] = fmaf(v, f3.x, acc[6]); acc[7] = fmaf(v, f3.y, acc[7]);
}

// ---------------- projection: accp[i][o0..o0+7] += ysm[i][b][:] @ W ----------------
__device__ __forceinline__ void project_acc(const float* __restrict__ wsm,
                                            const float* __restrict__ ysm,
                                            ull accp[RPB][4], int b, int o0) {
#pragma unroll 4
    for (int d = 0; d < Dd; d++) {
        const ull* wp = (const ull*)(wsm + d * OUTC + o0);
        ull w0 = wp[0], w1 = wp[1], w2 = wp[2], w3 = wp[3];
#pragma unroll
        for (int i = 0; i < RPB; i++) {
            float yv = ysm[(i * 32 + b) * YPAD + d];
            ull yv2 = pack2(yv, yv);
            ffma2(accp[i][0], yv2, w0);
            ffma2(accp[i][1], yv2, w1);
            ffma2(accp[i][2], yv2, w2);
            ffma2(accp[i][3], yv2, w3);
        }
    }
}

extern __shared__ float s_dyn[];

// ---------------- base pass: out = bias + x0 @ Wc ; also emits X16 ----------------
__global__ void __launch_bounds__(NT) base_k(const float* __restrict__ inputs,
                                             const float* __restrict__ bias,
                                             float* __restrict__ out) {
    float* wsm = s_dyn;
    float* ysm = s_dyn + Dd * OUTC;
    int t = threadIdx.x;
    for (int i = t; i < (Dd * OUTC) / 4; i += NT)
        ((float4*)wsm)[i] = ((const float4*)g_Wc)[i];

    int r0 = blockIdx.x * RPB;
    int bA = t >> 4, dA = (t & 15) * 4;

#pragma unroll
    for (int i = 0; i < RPB; i++) {
        int r = r0 + i;
        float4 a  = *(const float4*)(inputs + ((size_t)bA * Nn + r) * Dd + dA);
        float4 b2 = *(const float4*)(inputs + ((size_t)(bA + 16) * Nn + r) * Dd + dA);
        // emit fp16 X
        __half* xp0 = g_X16 + (size_t)r * WIDTH + bA * 64 + dA;
        __half* xp1 = g_X16 + (size_t)r * WIDTH + (bA + 16) * 64 + dA;
        *(__half2*)xp0       = __floats2half2_rn(a.x, a.y);
        *(__half2*)(xp0 + 2) = __floats2half2_rn(a.z, a.w);
        *(__half2*)xp1       = __floats2half2_rn(b2.x, b2.y);
        *(__half2*)(xp1 + 2) = __floats2half2_rn(b2.z, b2.w);
        // stage for projection
        *(float4*)&ysm[(i * 32 + bA) * YPAD + dA]      = a;
        *(float4*)&ysm[(i * 32 + bA + 16) * YPAD + dA] = b2;
    }
    __syncthreads();

    int b = t >> 3, o0 = (t & 7) * 8;
    ull accp[RPB][4];
#pragma unroll
    for (int i = 0; i < RPB; i++)
#pragma unroll
        for (int k = 0; k < 4; k++) accp[i][k] = 0ULL;

    project_acc(wsm, ysm, accp, b, o0);

    float4 bv0 = *(const float4*)(bias + o0);
    float4 bv1 = *(const float4*)(bias + o0 + 4);
#pragma unroll
    for (int i = 0; i < RPB; i++) {
        int r = r0 + i;
        float* op = out + ((size_t)b * Nn + r) * OUTC + o0;
        float4 e0, e1;
        unpack2(e0.x, e0.y, accp[i][0]); unpack2(e0.z, e0.w, accp[i][1]);
        unpack2(e1.x, e1.y, accp[i][2]); unpack2(e1.z, e1.w, accp[i][3]);
        e0.x += bv0.x; e0.y += bv0.y; e0.z += bv0.z; e0.w += bv0.w;
        e1.x += bv1.x; e1.y += bv1.y; e1.z += bv1.z; e1.w += bv1.w;
        *(float4*)op = e0;
        *(float4*)(op + 4) = e1;
    }
}

// ---------------- hop1: Y16 = A_s @ X16 (no projection) ----------------
__global__ void __launch_bounds__(NT) hop1_k(int s) {
    const int* __restrict__ rowptr = g_rowptr[s];
    const int* __restrict__ cols   = g_cols[s];
    const float* __restrict__ vals = g_vals[s];
    int t = threadIdx.x;
    int r0 = blockIdx.x * RPB;

    for (int i = 0; i < RPB; i++) {
        int r = r0 + i;
        float acc[8] = {0.f, 0.f, 0.f, 0.f, 0.f, 0.f, 0.f, 0.f};
        int j = rowptr[r], end = rowptr[r + 1];
        for (; j + 3 < end; j += 4) {
            int   c0 = cols[j], c1 = cols[j + 1], c2 = cols[j + 2], c3 = cols[j + 3];
            float v0 = vals[j], v1 = vals[j + 1], v2 = vals[j + 2], v3 = vals[j + 3];
            gacc(acc, v0, g_X16, c0, t);
            gacc(acc, v1, g_X16, c1, t);
            gacc(acc, v2, g_X16, c2, t);
            gacc(acc, v3, g_X16, c3, t);
        }
        for (; j < end; j++) gacc(acc, vals[j], g_X16, cols[j], t);

        uint4 h;
        __half2* hp = (__half2*)&h;
        hp[0] = __floats2half2_rn(acc[0], acc[1]);
        hp[1] = __floats2half2_rn(acc[2], acc[3]);
        hp[2] = __floats2half2_rn(acc[4], acc[5]);
        hp[3] = __floats2half2_rn(acc[6], acc[7]);
        *(uint4*)(g_Y16 + (size_t)r * WIDTH + t * 8) = h;
    }
}

// ---------------- hop2: Y2 = A_s @ Y16 ; out += Y@Wm1 + Y2@Wm2 ----------------
__global__ void __launch_bounds__(NT) hop2_k(const float* __restrict__ weight,
                                             float* __restrict__ out,
                                             int s, int m1, int m2) {
    float* wsm1 = s_dyn;                    // W for Y   (hop-1 result)
    float* wsm2 = s_dyn + Dd * OUTC;        // W for Y2
    float* ysm  = s_dyn + 2 * Dd * OUTC;

    int t = threadIdx.x;
    const float* W1g = weight + (size_t)m1 * Dd * OUTC;
    const float* W2g = weight + (size_t)m2 * Dd * OUTC;
    for (int i = t; i < (Dd * OUTC) / 4; i += NT) {
        ((float4*)wsm1)[i] = ((const float4*)W1g)[i];
        ((float4*)wsm2)[i] = ((const float4*)W2g)[i];
    }

    const int* __restrict__ rowptr = g_rowptr[s];
    const int* __restrict__ cols   = g_cols[s];
    const float* __restrict__ vals = g_vals[s];

    int r0 = blockIdx.x * RPB;
    int bg = t >> 3, d0 = (t & 7) * 8;   // gather-element mapping: e = t*8

    // phase A: gather Y2 rows, stage into ysm
    for (int i = 0; i < RPB; i++) {
        int r = r0 + i;
        float acc[8] = {0.f, 0.f, 0.f, 0.f, 0.f, 0.f, 0.f, 0.f};
        int j = rowptr[r], end = rowptr[r + 1];
        for (; j + 3 < end; j += 4) {
            int   c0 = cols[j], c1 = cols[j + 1], c2 = cols[j + 2], c3 = cols[j + 3];
            float v0 = vals[j], v1 = vals[j + 1], v2 = vals[j + 2], v3 = vals[j + 3];
            gacc(acc, v0, g_Y16, c0, t);
            gacc(acc, v1, g_Y16, c1, t);
            gacc(acc, v2, g_Y16, c2, t);
            gacc(acc, v3, g_Y16, c3, t);
        }
        for (; j < end; j++) gacc(acc, vals[j], g_Y16, cols[j], t);

        float* yd = &ysm[(i * 32 + bg) * YPAD + d0];
        *(float4*)yd       = make_float4(acc[0], acc[1], acc[2], acc[3]);
        *(float4*)(yd + 4) = make_float4(acc[4], acc[5], acc[6], acc[7]);
    }
    __syncthreads();

    int b = t >> 3, o0 = (t & 7) * 8;
    ull accp[RPB][4];
#pragma unroll
    for (int i = 0; i < RPB; i++)
#pragma unroll
        for (int k = 0; k < 4; k++) accp[i][k] = 0ULL;

    project_acc(wsm2, ysm, accp, b, o0);   // Y2 @ Wm2
    __syncthreads();

    // phase B: own-row Y into ysm
    for (int i = 0; i < RPB; i++) {
        int r = r0 + i;
        uint4 h = *(const uint4*)(g_Y16 + (size_t)r * WIDTH + t * 8);
        const __half2* hp = (const __half2*)&h;
        float2 f0 = __half22float2(hp[0]);
        float2 f1 = __half22float2(hp[1]);
        float2 f2 = __half22float2(hp[2]);
        float2 f3 = __half22float2(hp[3]);
        float* yd = &ysm[(i * 32 + bg) * YPAD + d0];
        *(float4*)yd       = make_float4(f0.x, f0.y, f1.x, f1.y);
        *(float4*)(yd + 4) = make_float4(f2.x, f2.y, f3.x, f3.y);
    }
    __syncthreads();

    project_acc(wsm1, ysm, accp, b, o0);   // Y @ Wm1

#pragma unroll
    for (int i = 0; i < RPB; i++) {
        int r = r0 + i;
        float* op = out + ((size_t)b * Nn + r) * OUTC + o0;
        float4 e0 = *(float4*)op;
        float4 e1 = *(float4*)(op + 4);
        float p0, p1;
        unpack2(p0, p1, accp[i][0]); e0.x += p0; e0.y += p1;
        unpack2(p0, p1, accp[i][1]); e0.z += p0; e0.w += p1;
        unpack2(p0, p1, accp[i][2]); e1.x += p0; e1.y += p1;
        unpack2(p0, p1, accp[i][3]); e1.z += p0; e1.w += p1;
        *(float4*)op       = e0;
        *(float4*)(op + 4) = e1;
    }
}

// ---------------- launch ----------------
extern "C" void kernel_launch(void* const* d_in, const int* in_sizes, int n_in,
                              void* d_out, int out_size) {
    const float* inputs = (const float*)d_in[0];
    const int*   r0     = (const int*)d_in[1];
    const int*   c0     = (const int*)d_in[2];
    const float* v0     = (const float*)d_in[3];
    const int*   r1     = (const int*)d_in[4];
    const int*   c1     = (const int*)d_in[5];
    const float* v1     = (const float*)d_in[6];
    const float* weight = (const float*)d_in[7];
    const float* bias   = (const float*)d_in[8];
    float* out = (float*)d_out;

    const size_t sh_base = (size_t)(Dd * OUTC + RPB * 32 * YPAD) * sizeof(float);      // 84 KB
    const size_t sh_hop2 = (size_t)(2 * Dd * OUTC + RPB * 32 * YPAD) * sizeof(float);  // 100 KB
    cudaFuncSetAttribute(base_k, cudaFuncAttributeMaxDynamicSharedMemorySize, (int)sh_base);
    cudaFuncSetAttribute(hop2_k, cudaFuncAttributeMaxDynamicSharedMemorySize, (int)sh_hop2);

    // CSR build (within-row order race-determined; fp32 jitter << 1e-3 gate)
    zero_counts_k<<<(2 * Nn + 255) / 256, 256>>>();
    hist_k<<<(2 * Ee + 255) / 256, 256>>>(r0, r1);
    scan_k<<<2, 1024>>>();
    scatter_k<<<(2 * Ee + 255) / 256, 256>>>(r0, c0, v0, r1, c1, v1);
    wc_k<<<(Dd * OUTC + 255) / 256, 256>>>(weight);

    const int NBLK = Nn / RPB;  // 2500

    base_k<<<NBLK, NT, sh_base>>>(inputs, bias, out);          // out = bias + x0@(W0+W3); X16
    hop1_k<<<NBLK, NT>>>(0);                                    // Y16 = A0 X16
    hop2_k<<<NBLK, NT, sh_hop2>>>(weight, out, 0, 1, 2);        // out += Y@W1 + (A0 Y)@W2
    hop1_k<<<NBLK, NT>>>(1);                                    // Y16 = A1 X16
    hop2_k<<<NBLK, NT, sh_hop2>>>(weight, out, 1, 4, 5);        // out += Y@W4 + (A1 Y)@W5
}

// round 10
// speedup vs baseline: 1.0018x; 1.0018x over previous
#include <cuda_runtime.h>
#include <cuda_fp16.h>

typedef unsigned long long ull;

#define Nn 20000
#define Dd 64
#define OUTC 64
#define WIDTH 2048   // B*D elements per node-row
#define Ee 640000
#define RPB 8
#define YPAD 68
#define NT 256

// ---------------- device scratch ----------------
__device__ __half g_X16[(size_t)Nn * WIDTH];   // 82 MB, fp16 x0
__device__ __half g_Y16[(size_t)Nn * WIDTH];   // 82 MB, fp16 A*x per support
__device__ int   g_rowptr[2][Nn + 1];
__device__ int   g_cnt[2][Nn];
__device__ int   g_fill[2][Nn];
__device__ int   g_cols[2][Ee];
__device__ float g_vals[2][Ee];
__device__ float g_Wc[Dd * OUTC];              // W0 + W3

// ---------------- packed f32x2 helpers ----------------
__device__ __forceinline__ ull pack2(float a, float b) {
    ull r; asm("mov.b64 %0, {%1, %2};" : "=l"(r) : "f"(a), "f"(b)); return r;
}
__device__ __forceinline__ void unpack2(float& a, float& b, ull p) {
    asm("mov.b64 {%0, %1}, %2;" : "=f"(a), "=f"(b) : "l"(p));
}
__device__ __forceinline__ void ffma2(ull& acc, ull a, ull b) {
    asm("fma.rn.f32x2 %0, %1, %2, %0;" : "+l"(acc) : "l"(a), "l"(b));
}

// ---------------- CSR build ----------------
__global__ void zero_counts_k() {
    int i = blockIdx.x * blockDim.x + threadIdx.x;
    if (i < 2 * Nn) { ((int*)g_cnt)[i] = 0; ((int*)g_fill)[i] = 0; }
}

__global__ void hist_k(const int* __restrict__ r0, const int* __restrict__ r1) {
    int i = blockIdx.x * blockDim.x + threadIdx.x;
    if (i < Ee)          atomicAdd(&g_cnt[0][r0[i]], 1);
    else if (i < 2 * Ee) atomicAdd(&g_cnt[1][r1[i - Ee]], 1);
}

__global__ void scan_k() {
    __shared__ int sums[1024];
    int s = blockIdx.x, t = threadIdx.x;
    const int CH = (Nn + 1023) / 1024;
    int base = t * CH, acc = 0;
    for (int i = 0; i < CH; i++) { int idx = base + i; if (idx < Nn) acc += g_cnt[s][idx]; }
    sums[t] = acc;
    __syncthreads();
    for (int off = 1; off < 1024; off <<= 1) {
        int v = (t >= off) ? sums[t - off] : 0;
        __syncthreads(); sums[t] += v; __syncthreads();
    }
    int run = (t > 0) ? sums[t - 1] : 0;
    for (int i = 0; i < CH; i++) {
        int idx = base + i;
        if (idx < Nn) { g_rowptr[s][idx] = run; run += g_cnt[s][idx]; }
    }
    if (t == 1023) g_rowptr[s][Nn] = sums[1023];
}

__global__ void scatter_k(const int* __restrict__ r0, const int* __restrict__ c0, const float* __restrict__ v0,
                          const int* __restrict__ r1, const int* __restrict__ c1, const float* __restrict__ v1) {
    int i = blockIdx.x * blockDim.x + threadIdx.x;
    int s, e; const int* rs; const int* cs; const float* vs;
    if (i < Ee)          { s = 0; e = i;      rs = r0; cs = c0; vs = v0; }
    else if (i < 2 * Ee) { s = 1; e = i - Ee; rs = r1; cs = c1; vs = v1; }
    else return;
    int row = rs[e];
    int pos = g_rowptr[s][row] + atomicAdd(&g_fill[s][row], 1);
    g_cols[s][pos] = cs[e];
    g_vals[s][pos] = vs[e];
}

__global__ void wc_k(const float* __restrict__ w) {
    int i = blockIdx.x * blockDim.x + threadIdx.x;
    if (i < Dd * OUTC) g_Wc[i] = w[i] + w[3 * Dd * OUTC + i];
}

// ---------------- gather accumulate (8 halves / thread / edge) ----------------
__device__ __forceinline__ void gacc(float acc[8], float v, const __half* __restrict__ src,
                                     int c, int t) {
    uint4 h = *(const uint4*)(src + (size_t)c * WIDTH + t * 8);
    const __half2* hp = (const __half2*)&h;
    float2 f0 = __half22float2(hp[0]);
    float2 f1 = __half22float2(hp[1]);
    float2 f2 = __half22float2(hp[2]);
    float2 f3 = __half22float2(hp[3]);
    acc[0] = fmaf(v, f0.x, acc[0]); acc[1] = fmaf(v, f0.y, acc[1]);
    acc[2] = fmaf(v, f1.x, acc[2]); acc[3] = fmaf(v, f1.y, acc[3]);
    acc[4] = fmaf(v, f2.x, acc[4]); acc[5] = fmaf(v, f2.y, acc[5]);
    acc[6] = fmaf(v, f3.x, acc[6]); acc[7] = fmaf(v, f3.y, acc[7]);
}

// ---------------- projection: accp[i][o0..o0+7] += ysm[i][b][:] @ W ----------------
__device__ __forceinline__ void project_acc(const float* __restrict__ wsm,
                                            const float* __restrict__ ysm,
                                            ull accp[RPB][4], int b, int o0) {
#pragma unroll 4
    for (int d = 0; d < Dd; d++) {
        const ull* wp = (const ull*)(wsm + d * OUTC + o0);
        ull w0 = wp[0], w1 = wp[1], w2 = wp[2], w3 = wp[3];
#pragma unroll
        for (int i = 0; i < RPB; i++) {
            float yv = ysm[(i * 32 + b) * YPAD + d];
            ull yv2 = pack2(yv, yv);
            ffma2(accp[i][0], yv2, w0);
            ffma2(accp[i][1], yv2, w1);
            ffma2(accp[i][2], yv2, w2);
            ffma2(accp[i][3], yv2, w3);
        }
    }
}

extern __shared__ float s_dyn[];

// ---------------- base pass: out = bias + x0 @ Wc ; also emits X16 ----------------
__global__ void __launch_bounds__(NT) base_k(const float* __restrict__ inputs,
                                             const float* __restrict__ bias,
                                             float* __restrict__ out) {
    float* wsm = s_dyn;
    float* ysm = s_dyn + Dd * OUTC;
    int t = threadIdx.x;
    for (int i = t; i < (Dd * OUTC) / 4; i += NT)
        ((float4*)wsm)[i] = ((const float4*)g_Wc)[i];

    int r0 = blockIdx.x * RPB;
    int bA = t >> 4, dA = (t & 15) * 4;

#pragma unroll
    for (int i = 0; i < RPB; i++) {
        int r = r0 + i;
        float4 a  = *(const float4*)(inputs + ((size_t)bA * Nn + r) * Dd + dA);
        float4 b2 = *(const float4*)(inputs + ((size_t)(bA + 16) * Nn + r) * Dd + dA);
        // emit fp16 X
        __half* xp0 = g_X16 + (size_t)r * WIDTH + bA * 64 + dA;
        __half* xp1 = g_X16 + (size_t)r * WIDTH + (bA + 16) * 64 + dA;
        *(__half2*)xp0       = __floats2half2_rn(a.x, a.y);
        *(__half2*)(xp0 + 2) = __floats2half2_rn(a.z, a.w);
        *(__half2*)xp1       = __floats2half2_rn(b2.x, b2.y);
        *(__half2*)(xp1 + 2) = __floats2half2_rn(b2.z, b2.w);
        // stage for projection
        *(float4*)&ysm[(i * 32 + bA) * YPAD + dA]      = a;
        *(float4*)&ysm[(i * 32 + bA + 16) * YPAD + dA] = b2;
    }
    __syncthreads();

    int b = t >> 3, o0 = (t & 7) * 8;
    ull accp[RPB][4];
#pragma unroll
    for (int i = 0; i < RPB; i++)
#pragma unroll
        for (int k = 0; k < 4; k++) accp[i][k] = 0ULL;

    project_acc(wsm, ysm, accp, b, o0);

    float4 bv0 = *(const float4*)(bias + o0);
    float4 bv1 = *(const float4*)(bias + o0 + 4);
#pragma unroll
    for (int i = 0; i < RPB; i++) {
        int r = r0 + i;
        float* op = out + ((size_t)b * Nn + r) * OUTC + o0;
        float4 e0, e1;
        unpack2(e0.x, e0.y, accp[i][0]); unpack2(e0.z, e0.w, accp[i][1]);
        unpack2(e1.x, e1.y, accp[i][2]); unpack2(e1.z, e1.w, accp[i][3]);
        e0.x += bv0.x; e0.y += bv0.y; e0.z += bv0.z; e0.w += bv0.w;
        e1.x += bv1.x; e1.y += bv1.y; e1.z += bv1.z; e1.w += bv1.w;
        *(float4*)op = e0;
        *(float4*)(op + 4) = e1;
    }
}

// ---------------- hop1: Y16 = A_s @ X16 (no projection) ----------------
__global__ void __launch_bounds__(NT) hop1_k(int s) {
    const int* __restrict__ rowptr = g_rowptr[s];
    const int* __restrict__ cols   = g_cols[s];
    const float* __restrict__ vals = g_vals[s];
    int t = threadIdx.x;
    int r0 = blockIdx.x * RPB;

    for (int i = 0; i < RPB; i++) {
        int r = r0 + i;
        float acc[8] = {0.f, 0.f, 0.f, 0.f, 0.f, 0.f, 0.f, 0.f};
        int j = rowptr[r], end = rowptr[r + 1];
        for (; j + 3 < end; j += 4) {
            int   c0 = cols[j], c1 = cols[j + 1], c2 = cols[j + 2], c3 = cols[j + 3];
            float v0 = vals[j], v1 = vals[j + 1], v2 = vals[j + 2], v3 = vals[j + 3];
            gacc(acc, v0, g_X16, c0, t);
            gacc(acc, v1, g_X16, c1, t);
            gacc(acc, v2, g_X16, c2, t);
            gacc(acc, v3, g_X16, c3, t);
        }
        for (; j < end; j++) gacc(acc, vals[j], g_X16, cols[j], t);

        uint4 h;
        __half2* hp = (__half2*)&h;
        hp[0] = __floats2half2_rn(acc[0], acc[1]);
        hp[1] = __floats2half2_rn(acc[2], acc[3]);
        hp[2] = __floats2half2_rn(acc[4], acc[5]);
        hp[3] = __floats2half2_rn(acc[6], acc[7]);
        *(uint4*)(g_Y16 + (size_t)r * WIDTH + t * 8) = h;
    }
}

// ---------------- hop2: Y2 = A_s @ Y16 ; out += Y@Wm1 + Y2@Wm2 ----------------
__global__ void __launch_bounds__(NT) hop2_k(const float* __restrict__ weight,
                                             float* __restrict__ out,
                                             int s, int m1, int m2) {
    float* wsm1 = s_dyn;                    // W for Y   (hop-1 result)
    float* wsm2 = s_dyn + Dd * OUTC;        // W for Y2
    float* ysm  = s_dyn + 2 * Dd * OUTC;

    int t = threadIdx.x;
    const float* W1g = weight + (size_t)m1 * Dd * OUTC;
    const float* W2g = weight + (size_t)m2 * Dd * OUTC;
    for (int i = t; i < (Dd * OUTC) / 4; i += NT) {
        ((float4*)wsm1)[i] = ((const float4*)W1g)[i];
        ((float4*)wsm2)[i] = ((const float4*)W2g)[i];
    }

    const int* __restrict__ rowptr = g_rowptr[s];
    const int* __restrict__ cols   = g_cols[s];
    const float* __restrict__ vals = g_vals[s];

    int r0 = blockIdx.x * RPB;
    int bg = t >> 3, d0 = (t & 7) * 8;   // gather-element mapping: e = t*8

    // phase A: gather Y2 rows, stage into ysm
    for (int i = 0; i < RPB; i++) {
        int r = r0 + i;
        float acc[8] = {0.f, 0.f, 0.f, 0.f, 0.f, 0.f, 0.f, 0.f};
        int j = rowptr[r], end = rowptr[r + 1];
        for (; j + 3 < end; j += 4) {
            int   c0 = cols[j], c1 = cols[j + 1], c2 = cols[j + 2], c3 = cols[j + 3];
            float v0 = vals[j], v1 = vals[j + 1], v2 = vals[j + 2], v3 = vals[j + 3];
            gacc(acc, v0, g_Y16, c0, t);
            gacc(acc, v1, g_Y16, c1, t);
            gacc(acc, v2, g_Y16, c2, t);
            gacc(acc, v3, g_Y16, c3, t);
        }
        for (; j < end; j++) gacc(acc, vals[j], g_Y16, cols[j], t);

        float* yd = &ysm[(i * 32 + bg) * YPAD + d0];
        *(float4*)yd       = make_float4(acc[0], acc[1], acc[2], acc[3]);
        *(float4*)(yd + 4) = make_float4(acc[4], acc[5], acc[6], acc[7]);
    }
    __syncthreads();

    int b = t >> 3, o0 = (t & 7) * 8;
    ull accp[RPB][4];
#pragma unroll
    for (int i = 0; i < RPB; i++)
#pragma unroll
        for (int k = 0; k < 4; k++) accp[i][k] = 0ULL;

    project_acc(wsm2, ysm, accp, b, o0);   // Y2 @ Wm2
    __syncthreads();

    // phase B: own-row Y into ysm
    for (int i = 0; i < RPB; i++) {
        int r = r0 + i;
        uint4 h = *(const uint4*)(g_Y16 + (size_t)r * WIDTH + t * 8);
        const __half2* hp = (const __half2*)&h;
        float2 f0 = __half22float2(hp[0]);
        float2 f1 = __half22float2(hp[1]);
        float2 f2 = __half22float2(hp[2]);
        float2 f3 = __half22float2(hp[3]);
        float* yd = &ysm[(i * 32 + bg) * YPAD + d0];
        *(float4*)yd       = make_float4(f0.x, f0.y, f1.x, f1.y);
        *(float4*)(yd + 4) = make_float4(f2.x, f2.y, f3.x, f3.y);
    }
    __syncthreads();

    project_acc(wsm1, ysm, accp, b, o0);   // Y @ Wm1

#pragma unroll
    for (int i = 0; i < RPB; i++) {
        int r = r0 + i;
        float* op = out + ((size_t)b * Nn + r) * OUTC + o0;
        float4 e0 = *(float4*)op;
        float4 e1 = *(float4*)(op + 4);
        float p0, p1;
        unpack2(p0, p1, accp[i][0]); e0.x += p0; e0.y += p1;
        unpack2(p0, p1, accp[i][1]); e0.z += p0; e0.w += p1;
        unpack2(p0, p1, accp[i][2]); e1.x += p0; e1.y += p1;
        unpack2(p0, p1, accp[i][3]); e1.z += p0; e1.w += p1;
        *(float4*)op       = e0;
        *(float4*)(op + 4) = e1;
    }
}

// ---------------- launch ----------------
extern "C" void kernel_launch(void* const* d_in, const int* in_sizes, int n_in,
                              void* d_out, int out_size) {
    const float* inputs = (const float*)d_in[0];
    const int*   r0     = (const int*)d_in[1];
    const int*   c0     = (const int*)d_in[2];
    const float* v0     = (const float*)d_in[3];
    const int*   r1     = (const int*)d_in[4];
    const int*   c1     = (const int*)d_in[5];
    const float* v1     = (const float*)d_in[6];
    const float* weight = (const float*)d_in[7];
    const float* bias   = (const float*)d_in[8];
    float* out = (float*)d_out;

    const size_t sh_base = (size_t)(Dd * OUTC + RPB * 32 * YPAD) * sizeof(float);      // 84 KB
    const size_t sh_hop2 = (size_t)(2 * Dd * OUTC + RPB * 32 * YPAD) * sizeof(float);  // 100 KB
    cudaFuncSetAttribute(base_k, cudaFuncAttributeMaxDynamicSharedMemorySize, (int)sh_base);
    cudaFuncSetAttribute(hop2_k, cudaFuncAttributeMaxDynamicSharedMemorySize, (int)sh_hop2);

    // CSR build (within-row order race-determined; fp32 jitter << 1e-3 gate)
    zero_counts_k<<<(2 * Nn + 255) / 256, 256>>>();
    hist_k<<<(2 * Ee + 255) / 256, 256>>>(r0, r1);
    scan_k<<<2, 1024>>>();
    scatter_k<<<(2 * Ee + 255) / 256, 256>>>(r0, c0, v0, r1, c1, v1);
    wc_k<<<(Dd * OUTC + 255) / 256, 256>>>(weight);

    const int NBLK = Nn / RPB;  // 2500

    base_k<<<NBLK, NT, sh_base>>>(inputs, bias, out);          // out = bias + x0@(W0+W3); X16
    hop1_k<<<NBLK, NT>>>(0);                                    // Y16 = A0 X16
    hop2_k<<<NBLK, NT, sh_hop2>>>(weight, out, 0, 1, 2);        // out += Y@W1 + (A0 Y)@W2
    hop1_k<<<NBLK, NT>>>(1);                                    // Y16 = A1 X16
    hop2_k<<<NBLK, NT, sh_hop2>>>(weight, out, 1, 4, 5);        // out += Y@W4 + (A1 Y)@W5
}

// round 15
// speedup vs baseline: 1.0027x; 1.0010x over previous
#include <cuda_runtime.h>
#include <cuda_fp16.h>

typedef unsigned long long ull;

#define Nn 20000
#define Dd 64
#define OUTC 64
#define WIDTH 2048   // B*D elements per node-row
#define Ee 640000
#define RPB 8
#define YPAD 68
#define NT 256

// ---------------- device scratch ----------------
__device__ __half g_X16[(size_t)Nn * WIDTH];   // 82 MB, fp16 x0
__device__ __half g_Y16[(size_t)Nn * WIDTH];   // 82 MB, fp16 A*x per support
__device__ int   g_rowptr[2][Nn + 1];
__device__ int   g_cnt[2][Nn];
__device__ int   g_fill[2][Nn];
__device__ int   g_cols[2][Ee];
__device__ float g_vals[2][Ee];
__device__ float g_Wc[Dd * OUTC];              // W0 + W3

// ---------------- packed f32x2 helpers ----------------
__device__ __forceinline__ ull pack2(float a, float b) {
    ull r; asm("mov.b64 %0, {%1, %2};" : "=l"(r) : "f"(a), "f"(b)); return r;
}
__device__ __forceinline__ void unpack2(float& a, float& b, ull p) {
    asm("mov.b64 {%0, %1}, %2;" : "=f"(a), "=f"(b) : "l"(p));
}
__device__ __forceinline__ void ffma2(ull& acc, ull a, ull b) {
    asm("fma.rn.f32x2 %0, %1, %2, %0;" : "+l"(acc) : "l"(a), "l"(b));
}

// ---------------- CSR build ----------------
__global__ void zero_counts_k() {
    int i = blockIdx.x * blockDim.x + threadIdx.x;
    if (i < 2 * Nn) { ((int*)g_cnt)[i] = 0; ((int*)g_fill)[i] = 0; }
}

__global__ void hist_k(const int* __restrict__ r0, const int* __restrict__ r1) {
    int i = blockIdx.x * blockDim.x + threadIdx.x;
    if (i < Ee)          atomicAdd(&g_cnt[0][r0[i]], 1);
    else if (i < 2 * Ee) atomicAdd(&g_cnt[1][r1[i - Ee]], 1);
}

__global__ void scan_k() {
    __shared__ int sums[1024];
    int s = blockIdx.x, t = threadIdx.x;
    const int CH = (Nn + 1023) / 1024;
    int base = t * CH, acc = 0;
    for (int i = 0; i < CH; i++) { int idx = base + i; if (idx < Nn) acc += g_cnt[s][idx]; }
    sums[t] = acc;
    __syncthreads();
    for (int off = 1; off < 1024; off <<= 1) {
        int v = (t >= off) ? sums[t - off] : 0;
        __syncthreads(); sums[t] += v; __syncthreads();
    }
    int run = (t > 0) ? sums[t - 1] : 0;
    for (int i = 0; i < CH; i++) {
        int idx = base + i;
        if (idx < Nn) { g_rowptr[s][idx] = run; run += g_cnt[s][idx]; }
    }
    if (t == 1023) g_rowptr[s][Nn] = sums[1023];
}

__global__ void scatter_k(const int* __restrict__ r0, const int* __restrict__ c0, const float* __restrict__ v0,
                          const int* __restrict__ r1, const int* __restrict__ c1, const float* __restrict__ v1) {
    int i = blockIdx.x * blockDim.x + threadIdx.x;
    int s, e; const int* rs; const int* cs; const float* vs;
    if (i < Ee)          { s = 0; e = i;      rs = r0; cs = c0; vs = v0; }
    else if (i < 2 * Ee) { s = 1; e = i - Ee; rs = r1; cs = c1; vs = v1; }
    else return;
    int row = rs[e];
    int pos = g_rowptr[s][row] + atomicAdd(&g_fill[s][row], 1);
    g_cols[s][pos] = cs[e];
    g_vals[s][pos] = vs[e];
}

__global__ void wc_k(const float* __restrict__ w) {
    int i = blockIdx.x * blockDim.x + threadIdx.x;
    if (i < Dd * OUTC) g_Wc[i] = w[i] + w[3 * Dd * OUTC + i];
}

// ---------------- gather accumulate (8 halves / thread / edge) ----------------
__device__ __forceinline__ void gacc(float acc[8], float v, const __half* __restrict__ src,
                                     int c, int t) {
    uint4 h = *(const uint4*)(src + (size_t)c * WIDTH + t * 8);
    const __half2* hp = (const __half2*)&h;
    float2 f0 = __half22float2(hp[0]);
    float2 f1 = __half22float2(hp[1]);
    float2 f2 = __half22float2(hp[2]);
    float2 f3 = __half22float2(hp[3]);
    acc[0] = fmaf(v, f0.x, acc[0]); acc[1] = fmaf(v, f0.y, acc[1]);
    acc[2] = fmaf(v, f1.x, acc[2]); acc[3] = fmaf(v, f1.y, acc[3]);
    acc[4] = fmaf(v, f2.x, acc[4]); acc[5] = fmaf(v, f2.y, acc[5]);
    acc[6] = fmaf(v, f3.x, acc[6]); acc[7] = fmaf(v, f3.y, acc[7]);
}

// ---------------- projection: accp[i][o0..o0+7] += ysm[i][b][:] @ W ----------------
__device__ __forceinline__ void project_acc(const float* __restrict__ wsm,
                                            const float* __restrict__ ysm,
                                            ull accp[RPB][4], int b, int o0) {
#pragma unroll 4
    for (int d = 0; d < Dd; d++) {
        const ull* wp = (const ull*)(wsm + d * OUTC + o0);
        ull w0 = wp[0], w1 = wp[1], w2 = wp[2], w3 = wp[3];
#pragma unroll
        for (int i = 0; i < RPB; i++) {
            float yv = ysm[(i * 32 + b) * YPAD + d];
            ull yv2 = pack2(yv, yv);
            ffma2(accp[i][0], yv2, w0);
            ffma2(accp[i][1], yv2, w1);
            ffma2(accp[i][2], yv2, w2);
            ffma2(accp[i][3], yv2, w3);
        }
    }
}

extern __shared__ float s_dyn[];

// ---------------- base pass: out = bias + x0 @ Wc ; also emits X16 ----------------
__global__ void __launch_bounds__(NT) base_k(const float* __restrict__ inputs,
                                             const float* __restrict__ bias,
                                             float* __restrict__ out) {
    float* wsm = s_dyn;
    float* ysm = s_dyn + Dd * OUTC;
    int t = threadIdx.x;
    for (int i = t; i < (Dd * OUTC) / 4; i += NT)
        ((float4*)wsm)[i] = ((const float4*)g_Wc)[i];

    int r0 = blockIdx.x * RPB;
    int bA = t >> 4, dA = (t & 15) * 4;

#pragma unroll
    for (int i = 0; i < RPB; i++) {
        int r = r0 + i;
        float4 a  = *(const float4*)(inputs + ((size_t)bA * Nn + r) * Dd + dA);
        float4 b2 = *(const float4*)(inputs + ((size_t)(bA + 16) * Nn + r) * Dd + dA);
        // emit fp16 X
        __half* xp0 = g_X16 + (size_t)r * WIDTH + bA * 64 + dA;
        __half* xp1 = g_X16 + (size_t)r * WIDTH + (bA + 16) * 64 + dA;
        *(__half2*)xp0       = __floats2half2_rn(a.x, a.y);
        *(__half2*)(xp0 + 2) = __floats2half2_rn(a.z, a.w);
        *(__half2*)xp1       = __floats2half2_rn(b2.x, b2.y);
        *(__half2*)(xp1 + 2) = __floats2half2_rn(b2.z, b2.w);
        // stage for projection
        *(float4*)&ysm[(i * 32 + bA) * YPAD + dA]      = a;
        *(float4*)&ysm[(i * 32 + bA + 16) * YPAD + dA] = b2;
    }
    __syncthreads();

    int b = t >> 3, o0 = (t & 7) * 8;
    ull accp[RPB][4];
#pragma unroll
    for (int i = 0; i < RPB; i++)
#pragma unroll
        for (int k = 0; k < 4; k++) accp[i][k] = 0ULL;

    project_acc(wsm, ysm, accp, b, o0);

    float4 bv0 = *(const float4*)(bias + o0);
    float4 bv1 = *(const float4*)(bias + o0 + 4);
#pragma unroll
    for (int i = 0; i < RPB; i++) {
        int r = r0 + i;
        float* op = out + ((size_t)b * Nn + r) * OUTC + o0;
        float4 e0, e1;
        unpack2(e0.x, e0.y, accp[i][0]); unpack2(e0.z, e0.w, accp[i][1]);
        unpack2(e1.x, e1.y, accp[i][2]); unpack2(e1.z, e1.w, accp[i][3]);
        e0.x += bv0.x; e0.y += bv0.y; e0.z += bv0.z; e0.w += bv0.w;
        e1.x += bv1.x; e1.y += bv1.y; e1.z += bv1.z; e1.w += bv1.w;
        *(float4*)op = e0;
        *(float4*)(op + 4) = e1;
    }
}

// ---------------- hop1: Y16 = A_s @ X16 (no projection) ----------------
__global__ void __launch_bounds__(NT) hop1_k(int s) {
    const int* __restrict__ rowptr = g_rowptr[s];
    const int* __restrict__ cols   = g_cols[s];
    const float* __restrict__ vals = g_vals[s];
    int t = threadIdx.x;
    int r0 = blockIdx.x * RPB;

    for (int i = 0; i < RPB; i++) {
        int r = r0 + i;
        float acc[8] = {0.f, 0.f, 0.f, 0.f, 0.f, 0.f, 0.f, 0.f};
        int j = rowptr[r], end = rowptr[r + 1];
        for (; j + 3 < end; j += 4) {
            int   c0 = cols[j], c1 = cols[j + 1], c2 = cols[j + 2], c3 = cols[j + 3];
            float v0 = vals[j], v1 = vals[j + 1], v2 = vals[j + 2], v3 = vals[j + 3];
            gacc(acc, v0, g_X16, c0, t);
            gacc(acc, v1, g_X16, c1, t);
            gacc(acc, v2, g_X16, c2, t);
            gacc(acc, v3, g_X16, c3, t);
        }
        for (; j < end; j++) gacc(acc, vals[j], g_X16, cols[j], t);

        uint4 h;
        __half2* hp = (__half2*)&h;
        hp[0] = __floats2half2_rn(acc[0], acc[1]);
        hp[1] = __floats2half2_rn(acc[2], acc[3]);
        hp[2] = __floats2half2_rn(acc[4], acc[5]);
        hp[3] = __floats2half2_rn(acc[6], acc[7]);
        *(uint4*)(g_Y16 + (size_t)r * WIDTH + t * 8) = h;
    }
}

// ---------------- hop2: Y2 = A_s @ Y16 ; out += Y@Wm1 + Y2@Wm2 ----------------
__global__ void __launch_bounds__(NT) hop2_k(const float* __restrict__ weight,
                                             float* __restrict__ out,
                                             int s, int m1, int m2) {
    float* wsm1 = s_dyn;                    // W for Y   (hop-1 result)
    float* wsm2 = s_dyn + Dd * OUTC;        // W for Y2
    float* ysm  = s_dyn + 2 * Dd * OUTC;

    int t = threadIdx.x;
    const float* W1g = weight + (size_t)m1 * Dd * OUTC;
    const float* W2g = weight + (size_t)m2 * Dd * OUTC;
    for (int i = t; i < (Dd * OUTC) / 4; i += NT) {
        ((float4*)wsm1)[i] = ((const float4*)W1g)[i];
        ((float4*)wsm2)[i] = ((const float4*)W2g)[i];
    }

    const int* __restrict__ rowptr = g_rowptr[s];
    const int* __restrict__ cols   = g_cols[s];
    const float* __restrict__ vals = g_vals[s];

    int r0 = blockIdx.x * RPB;
    int bg = t >> 3, d0 = (t & 7) * 8;   // gather-element mapping: e = t*8

    // phase A: gather Y2 rows, stage into ysm
    for (int i = 0; i < RPB; i++) {
        int r = r0 + i;
        float acc[8] = {0.f, 0.f, 0.f, 0.f, 0.f, 0.f, 0.f, 0.f};
        int j = rowptr[r], end = rowptr[r + 1];
        for (; j + 3 < end; j += 4) {
            int   c0 = cols[j], c1 = cols[j + 1], c2 = cols[j + 2], c3 = cols[j + 3];
            float v0 = vals[j], v1 = vals[j + 1], v2 = vals[j + 2], v3 = vals[j + 3];
            gacc(acc, v0, g_Y16, c0, t);
            gacc(acc, v1, g_Y16, c1, t);
            gacc(acc, v2, g_Y16, c2, t);
            gacc(acc, v3, g_Y16, c3, t);
        }
        for (; j < end; j++) gacc(acc, vals[j], g_Y16, cols[j], t);

        float* yd = &ysm[(i * 32 + bg) * YPAD + d0];
        *(float4*)yd       = make_float4(acc[0], acc[1], acc[2], acc[3]);
        *(float4*)(yd + 4) = make_float4(acc[4], acc[5], acc[6], acc[7]);
    }
    __syncthreads();

    int b = t >> 3, o0 = (t & 7) * 8;
    ull accp[RPB][4];
#pragma unroll
    for (int i = 0; i < RPB; i++)
#pragma unroll
        for (int k = 0; k < 4; k++) accp[i][k] = 0ULL;

    project_acc(wsm2, ysm, accp, b, o0);   // Y2 @ Wm2
    __syncthreads();

    // phase B: own-row Y into ysm
    for (int i = 0; i < RPB; i++) {
        int r = r0 + i;
        uint4 h = *(const uint4*)(g_Y16 + (size_t)r * WIDTH + t * 8);
        const __half2* hp = (const __half2*)&h;
        float2 f0 = __half22float2(hp[0]);
        float2 f1 = __half22float2(hp[1]);
        float2 f2 = __half22float2(hp[2]);
        float2 f3 = __half22float2(hp[3]);
        float* yd = &ysm[(i * 32 + bg) * YPAD + d0];
        *(float4*)yd       = make_float4(f0.x, f0.y, f1.x, f1.y);
        *(float4*)(yd + 4) = make_float4(f2.x, f2.y, f3.x, f3.y);
    }
    __syncthreads();

    project_acc(wsm1, ysm, accp, b, o0);   // Y @ Wm1

#pragma unroll
    for (int i = 0; i < RPB; i++) {
        int r = r0 + i;
        float* op = out + ((size_t)b * Nn + r) * OUTC + o0;
        float4 e0 = *(float4*)op;
        float4 e1 = *(float4*)(op + 4);
        float p0, p1;
        unpack2(p0, p1, accp[i][0]); e0.x += p0; e0.y += p1;
        unpack2(p0, p1, accp[i][1]); e0.z += p0; e0.w += p1;
        unpack2(p0, p1, accp[i][2]); e1.x += p0; e1.y += p1;
        unpack2(p0, p1, accp[i][3]); e1.z += p0; e1.w += p1;
        *(float4*)op       = e0;
        *(float4*)(op + 4) = e1;
    }
}

// ---------------- launch ----------------
extern "C" void kernel_launch(void* const* d_in, const int* in_sizes, int n_in,
                              void* d_out, int out_size) {
    const float* inputs = (const float*)d_in[0];
    const int*   r0     = (const int*)d_in[1];
    const int*   c0     = (const int*)d_in[2];
    const float* v0     = (const float*)d_in[3];
    const int*   r1     = (const int*)d_in[4];
    const int*   c1     = (const int*)d_in[5];
    const float* v1     = (const float*)d_in[6];
    const float* weight = (const float*)d_in[7];
    const float* bias   = (const float*)d_in[8];
    float* out = (float*)d_out;

    const size_t sh_base = (size_t)(Dd * OUTC + RPB * 32 * YPAD) * sizeof(float);      // 84 KB
    const size_t sh_hop2 = (size_t)(2 * Dd * OUTC + RPB * 32 * YPAD) * sizeof(float);  // 100 KB
    cudaFuncSetAttribute(base_k, cudaFuncAttributeMaxDynamicSharedMemorySize, (int)sh_base);
    cudaFuncSetAttribute(hop2_k, cudaFuncAttributeMaxDynamicSharedMemorySize, (int)sh_hop2);

    // CSR build (within-row order race-determined; fp32 jitter << 1e-3 gate)
    zero_counts_k<<<(2 * Nn + 255) / 256, 256>>>();
    hist_k<<<(2 * Ee + 255) / 256, 256>>>(r0, r1);
    scan_k<<<2, 1024>>>();
    scatter_k<<<(2 * Ee + 255) / 256, 256>>>(r0, c0, v0, r1, c1, v1);
    wc_k<<<(Dd * OUTC + 255) / 256, 256>>>(weight);

    const int NBLK = Nn / RPB;  // 2500

    base_k<<<NBLK, NT, sh_base>>>(inputs, bias, out);          // out = bias + x0@(W0+W3); X16
    hop1_k<<<NBLK, NT>>>(0);                                    // Y16 = A0 X16
    hop2_k<<<NBLK, NT, sh_hop2>>>(weight, out, 0, 1, 2);        // out += Y@W1 + (A0 Y)@W2
    hop1_k<<<NBLK, NT>>>(1);                                    // Y16 = A1 X16
    hop2_k<<<NBLK, NT, sh_hop2>>>(weight, out, 1, 4, 5);        // out += Y@W4 + (A1 Y)@W5
}

// round 17
// speedup vs baseline: 1.0041x; 1.0014x over previous
#include <cuda_runtime.h>
#include <cuda_fp16.h>

typedef unsigned long long ull;

#define Nn 20000
#define Dd 64
#define OUTC 64
#define WIDTH 2048   // B*D elements per node-row
#define Ee 640000
#define RPB 8
#define YPAD 68
#define NT 256

// ---------------- device scratch ----------------
__device__ __half g_X16[(size_t)Nn * WIDTH];   // 82 MB, fp16 x0
__device__ __half g_Y16[(size_t)Nn * WIDTH];   // 82 MB, fp16 A*x per support
__device__ int   g_rowptr[2][Nn + 1];
__device__ int   g_cnt[2][Nn];
__device__ int   g_fill[2][Nn];
__device__ int   g_cols[2][Ee];
__device__ float g_vals[2][Ee];
__device__ float g_Wc[Dd * OUTC];              // W0 + W3

// ---------------- packed f32x2 helpers ----------------
__device__ __forceinline__ ull pack2(float a, float b) {
    ull r; asm("mov.b64 %0, {%1, %2};" : "=l"(r) : "f"(a), "f"(b)); return r;
}
__device__ __forceinline__ void unpack2(float& a, float& b, ull p) {
    asm("mov.b64 {%0, %1}, %2;" : "=f"(a), "=f"(b) : "l"(p));
}
__device__ __forceinline__ void ffma2(ull& acc, ull a, ull b) {
    asm("fma.rn.f32x2 %0, %1, %2, %0;" : "+l"(acc) : "l"(a), "l"(b));
}

// ---------------- CSR build ----------------
__global__ void zero_counts_k() {
    int i = blockIdx.x * blockDim.x + threadIdx.x;
    if (i < 2 * Nn) { ((int*)g_cnt)[i] = 0; ((int*)g_fill)[i] = 0; }
}

__global__ void hist_k(const int* __restrict__ r0, const int* __restrict__ r1) {
    int i = blockIdx.x * blockDim.x + threadIdx.x;
    if (i < Ee)          atomicAdd(&g_cnt[0][r0[i]], 1);
    else if (i < 2 * Ee) atomicAdd(&g_cnt[1][r1[i - Ee]], 1);
}

__global__ void scan_k() {
    __shared__ int sums[1024];
    int s = blockIdx.x, t = threadIdx.x;
    const int CH = (Nn + 1023) / 1024;
    int base = t * CH, acc = 0;
    for (int i = 0; i < CH; i++) { int idx = base + i; if (idx < Nn) acc += g_cnt[s][idx]; }
    sums[t] = acc;
    __syncthreads();
    for (int off = 1; off < 1024; off <<= 1) {
        int v = (t >= off) ? sums[t - off] : 0;
        __syncthreads(); sums[t] += v; __syncthreads();
    }
    int run = (t > 0) ? sums[t - 1] : 0;
    for (int i = 0; i < CH; i++) {
        int idx = base + i;
        if (idx < Nn) { g_rowptr[s][idx] = run; run += g_cnt[s][idx]; }
    }
    if (t == 1023) g_rowptr[s][Nn] = sums[1023];
}

__global__ void scatter_k(const int* __restrict__ r0, const int* __restrict__ c0, const float* __restrict__ v0,
                          const int* __restrict__ r1, const int* __restrict__ c1, const float* __restrict__ v1) {
    int i = blockIdx.x * blockDim.x + threadIdx.x;
    int s, e; const int* rs; const int* cs; const float* vs;
    if (i < Ee)          { s = 0; e = i;      rs = r0; cs = c0; vs = v0; }
    else if (i < 2 * Ee) { s = 1; e = i - Ee; rs = r1; cs = c1; vs = v1; }
    else return;
    int row = rs[e];
    int pos = g_rowptr[s][row] + atomicAdd(&g_fill[s][row], 1);
    g_cols[s][pos] = cs[e];
    g_vals[s][pos] = vs[e];
}

__global__ void wc_k(const float* __restrict__ w) {
    int i = blockIdx.x * blockDim.x + threadIdx.x;
    if (i < Dd * OUTC) g_Wc[i] = w[i] + w[3 * Dd * OUTC + i];
}

// ---------------- gather accumulate (8 halves / thread / edge) ----------------
__device__ __forceinline__ void gacc(float acc[8], float v, const __half* __restrict__ src,
                                     int c, int t) {
    uint4 h = *(const uint4*)(src + (size_t)c * WIDTH + t * 8);
    const __half2* hp = (const __half2*)&h;
    float2 f0 = __half22float2(hp[0]);
    float2 f1 = __half22float2(hp[1]);
    float2 f2 = __half22float2(hp[2]);
    float2 f3 = __half22float2(hp[3]);
    acc[0] = fmaf(v, f0.x, acc[0]); acc[1] = fmaf(v, f0.y, acc[1]);
    acc[2] = fmaf(v, f1.x, acc[2]); acc[3] = fmaf(v, f1.y, acc[3]);
    acc[4] = fmaf(v, f2.x, acc[4]); acc[5] = fmaf(v, f2.y, acc[5]);
    acc[6] = fmaf(v, f3.x, acc[6]); acc[7] = fmaf(v, f3.y, acc[7]);
}

// ---------------- projection: accp[i][o0..o0+7] += ysm[i][b][:] @ W ----------------
__device__ __forceinline__ void project_acc(const float* __restrict__ wsm,
                                            const float* __restrict__ ysm,
                                            ull accp[RPB][4], int b, int o0) {
#pragma unroll 4
    for (int d = 0; d < Dd; d++) {
        const ull* wp = (const ull*)(wsm + d * OUTC + o0);
        ull w0 = wp[0], w1 = wp[1], w2 = wp[2], w3 = wp[3];
#pragma unroll
        for (int i = 0; i < RPB; i++) {
            float yv = ysm[(i * 32 + b) * YPAD + d];
            ull yv2 = pack2(yv, yv);
            ffma2(accp[i][0], yv2, w0);
            ffma2(accp[i][1], yv2, w1);
            ffma2(accp[i][2], yv2, w2);
            ffma2(accp[i][3], yv2, w3);
        }
    }
}

extern __shared__ float s_dyn[];

// ---------------- base pass: out = bias + x0 @ Wc ; also emits X16 ----------------
__global__ void __launch_bounds__(NT) base_k(const float* __restrict__ inputs,
                                             const float* __restrict__ bias,
                                             float* __restrict__ out) {
    float* wsm = s_dyn;
    float* ysm = s_dyn + Dd * OUTC;
    int t = threadIdx.x;
    for (int i = t; i < (Dd * OUTC) / 4; i += NT)
        ((float4*)wsm)[i] = ((const float4*)g_Wc)[i];

    int r0 = blockIdx.x * RPB;
    int bA = t >> 4, dA = (t & 15) * 4;

#pragma unroll
    for (int i = 0; i < RPB; i++) {
        int r = r0 + i;
        float4 a  = *(const float4*)(inputs + ((size_t)bA * Nn + r) * Dd + dA);
        float4 b2 = *(const float4*)(inputs + ((size_t)(bA + 16) * Nn + r) * Dd + dA);
        // emit fp16 X
        __half* xp0 = g_X16 + (size_t)r * WIDTH + bA * 64 + dA;
        __half* xp1 = g_X16 + (size_t)r * WIDTH + (bA + 16) * 64 + dA;
        *(__half2*)xp0       = __floats2half2_rn(a.x, a.y);
        *(__half2*)(xp0 + 2) = __floats2half2_rn(a.z, a.w);
        *(__half2*)xp1       = __floats2half2_rn(b2.x, b2.y);
        *(__half2*)(xp1 + 2) = __floats2half2_rn(b2.z, b2.w);
        // stage for projection
        *(float4*)&ysm[(i * 32 + bA) * YPAD + dA]      = a;
        *(float4*)&ysm[(i * 32 + bA + 16) * YPAD + dA] = b2;
    }
    __syncthreads();

    int b = t >> 3, o0 = (t & 7) * 8;
    ull accp[RPB][4];
#pragma unroll
    for (int i = 0; i < RPB; i++)
#pragma unroll
        for (int k = 0; k < 4; k++) accp[i][k] = 0ULL;

    project_acc(wsm, ysm, accp, b, o0);

    float4 bv0 = *(const float4*)(bias + o0);
    float4 bv1 = *(const float4*)(bias + o0 + 4);
#pragma unroll
    for (int i = 0; i < RPB; i++) {
        int r = r0 + i;
        float* op = out + ((size_t)b * Nn + r) * OUTC + o0;
        float4 e0, e1;
        unpack2(e0.x, e0.y, accp[i][0]); unpack2(e0.z, e0.w, accp[i][1]);
        unpack2(e1.x, e1.y, accp[i][2]); unpack2(e1.z, e1.w, accp[i][3]);
        e0.x += bv0.x; e0.y += bv0.y; e0.z += bv0.z; e0.w += bv0.w;
        e1.x += bv1.x; e1.y += bv1.y; e1.z += bv1.z; e1.w += bv1.w;
        *(float4*)op = e0;
        *(float4*)(op + 4) = e1;
    }
}

// ---------------- hop1: Y16 = A_s @ X16 (no projection) ----------------
__global__ void __launch_bounds__(NT) hop1_k(int s) {
    const int* __restrict__ rowptr = g_rowptr[s];
    const int* __restrict__ cols   = g_cols[s];
    const float* __restrict__ vals = g_vals[s];
    int t = threadIdx.x;
    int r0 = blockIdx.x * RPB;

    for (int i = 0; i < RPB; i++) {
        int r = r0 + i;
        float acc[8] = {0.f, 0.f, 0.f, 0.f, 0.f, 0.f, 0.f, 0.f};
        int j = rowptr[r], end = rowptr[r + 1];
        for (; j + 3 < end; j += 4) {
            int   c0 = cols[j], c1 = cols[j + 1], c2 = cols[j + 2], c3 = cols[j + 3];
            float v0 = vals[j], v1 = vals[j + 1], v2 = vals[j + 2], v3 = vals[j + 3];
            gacc(acc, v0, g_X16, c0, t);
            gacc(acc, v1, g_X16, c1, t);
            gacc(acc, v2, g_X16, c2, t);
            gacc(acc, v3, g_X16, c3, t);
        }
        for (; j < end; j++) gacc(acc, vals[j], g_X16, cols[j], t);

        uint4 h;
        __half2* hp = (__half2*)&h;
        hp[0] = __floats2half2_rn(acc[0], acc[1]);
        hp[1] = __floats2half2_rn(acc[2], acc[3]);
        hp[2] = __floats2half2_rn(acc[4], acc[5]);
        hp[3] = __floats2half2_rn(acc[6], acc[7]);
        *(uint4*)(g_Y16 + (size_t)r * WIDTH + t * 8) = h;
    }
}

// ---------------- hop2: Y2 = A_s @ Y16 ; out += Y@Wm1 + Y2@Wm2 ----------------
__global__ void __launch_bounds__(NT) hop2_k(const float* __restrict__ weight,
                                             float* __restrict__ out,
                                             int s, int m1, int m2) {
    float* wsm1 = s_dyn;                    // W for Y   (hop-1 result)
    float* wsm2 = s_dyn + Dd * OUTC;        // W for Y2
    float* ysm  = s_dyn + 2 * Dd * OUTC;

    int t = threadIdx.x;
    const float* W1g = weight + (size_t)m1 * Dd * OUTC;
    const float* W2g = weight + (size_t)m2 * Dd * OUTC;
    for (int i = t; i < (Dd * OUTC) / 4; i += NT) {
        ((float4*)wsm1)[i] = ((const float4*)W1g)[i];
        ((float4*)wsm2)[i] = ((const float4*)W2g)[i];
    }

    const int* __restrict__ rowptr = g_rowptr[s];
    const int* __restrict__ cols   = g_cols[s];
    const float* __restrict__ vals = g_vals[s];

    int r0 = blockIdx.x * RPB;
    int bg = t >> 3, d0 = (t & 7) * 8;   // gather-element mapping: e = t*8

    // phase A: gather Y2 rows, stage into ysm
    for (int i = 0; i < RPB; i++) {
        int r = r0 + i;
        float acc[8] = {0.f, 0.f, 0.f, 0.f, 0.f, 0.f, 0.f, 0.f};
        int j = rowptr[r], end = rowptr[r + 1];
        for (; j + 3 < end; j += 4) {
            int   c0 = cols[j], c1 = cols[j + 1], c2 = cols[j + 2], c3 = cols[j + 3];
            float v0 = vals[j], v1 = vals[j + 1], v2 = vals[j + 2], v3 = vals[j + 3];
            gacc(acc, v0, g_Y16, c0, t);
            gacc(acc, v1, g_Y16, c1, t);
            gacc(acc, v2, g_Y16, c2, t);
            gacc(acc, v3, g_Y16, c3, t);
        }
        for (; j < end; j++) gacc(acc, vals[j], g_Y16, cols[j], t);

        float* yd = &ysm[(i * 32 + bg) * YPAD + d0];
        *(float4*)yd       = make_float4(acc[0], acc[1], acc[2], acc[3]);
        *(float4*)(yd + 4) = make_float4(acc[4], acc[5], acc[6], acc[7]);
    }
    __syncthreads();

    int b = t >> 3, o0 = (t & 7) * 8;
    ull accp[RPB][4];
#pragma unroll
    for (int i = 0; i < RPB; i++)
#pragma unroll
        for (int k = 0; k < 4; k++) accp[i][k] = 0ULL;

    project_acc(wsm2, ysm, accp, b, o0);   // Y2 @ Wm2
    __syncthreads();

    // phase B: own-row Y into ysm
    for (int i = 0; i < RPB; i++) {
        int r = r0 + i;
        uint4 h = *(const uint4*)(g_Y16 + (size_t)r * WIDTH + t * 8);
        const __half2* hp = (const __half2*)&h;
        float2 f0 = __half22float2(hp[0]);
        float2 f1 = __half22float2(hp[1]);
        float2 f2 = __half22float2(hp[2]);
        float2 f3 = __half22float2(hp[3]);
        float* yd = &ysm[(i * 32 + bg) * YPAD + d0];
        *(float4*)yd       = make_float4(f0.x, f0.y, f1.x, f1.y);
        *(float4*)(yd + 4) = make_float4(f2.x, f2.y, f3.x, f3.y);
    }
    __syncthreads();

    project_acc(wsm1, ysm, accp, b, o0);   // Y @ Wm1

#pragma unroll
    for (int i = 0; i < RPB; i++) {
        int r = r0 + i;
        float* op = out + ((size_t)b * Nn + r) * OUTC + o0;
        float4 e0 = *(float4*)op;
        float4 e1 = *(float4*)(op + 4);
        float p0, p1;
        unpack2(p0, p1, accp[i][0]); e0.x += p0; e0.y += p1;
        unpack2(p0, p1, accp[i][1]); e0.z += p0; e0.w += p1;
        unpack2(p0, p1, accp[i][2]); e1.x += p0; e1.y += p1;
        unpack2(p0, p1, accp[i][3]); e1.z += p0; e1.w += p1;
        *(float4*)op       = e0;
        *(float4*)(op + 4) = e1;
    }
}

// ---------------- launch ----------------
extern "C" void kernel_launch(void* const* d_in, const int* in_sizes, int n_in,
                              void* d_out, int out_size) {
    const float* inputs = (const float*)d_in[0];
    const int*   r0     = (const int*)d_in[1];
    const int*   c0     = (const int*)d_in[2];
    const float* v0     = (const float*)d_in[3];
    const int*   r1     = (const int*)d_in[4];
    const int*   c1     = (const int*)d_in[5];
    const float* v1     = (const float*)d_in[6];
    const float* weight = (const float*)d_in[7];
    const float* bias   = (const float*)d_in[8];
    float* out = (float*)d_out;

    const size_t sh_base = (size_t)(Dd * OUTC + RPB * 32 * YPAD) * sizeof(float);      // 84 KB
    const size_t sh_hop2 = (size_t)(2 * Dd * OUTC + RPB * 32 * YPAD) * sizeof(float);  // 100 KB
    cudaFuncSetAttribute(base_k, cudaFuncAttributeMaxDynamicSharedMemorySize, (int)sh_base);
    cudaFuncSetAttribute(hop2_k, cudaFuncAttributeMaxDynamicSharedMemorySize, (int)sh_hop2);

    // CSR build (within-row order race-determined; fp32 jitter << 1e-3 gate)
    zero_counts_k<<<(2 * Nn + 255) / 256, 256>>>();
    hist_k<<<(2 * Ee + 255) / 256, 256>>>(r0, r1);
    scan_k<<<2, 1024>>>();
    scatter_k<<<(2 * Ee + 255) / 256, 256>>>(r0, c0, v0, r1, c1, v1);
    wc_k<<<(Dd * OUTC + 255) / 256, 256>>>(weight);

    const int NBLK = Nn / RPB;  // 2500

    base_k<<<NBLK, NT, sh_base>>>(inputs, bias, out);          // out = bias + x0@(W0+W3); X16
    hop1_k<<<NBLK, NT>>>(0);                                    // Y16 = A0 X16
    hop2_k<<<NBLK, NT, sh_hop2>>>(weight, out, 0, 1, 2);        // out += Y@W1 + (A0 Y)@W2
    hop1_k<<<NBLK, NT>>>(1);                                    // Y16 = A1 X16
    hop2_k<<<NBLK, NT, sh_hop2>>>(weight, out, 1, 4, 5);        // out += Y@W4 + (A1 Y)@W5
}